// round 7
// baseline (speedup 1.0000x reference)
#include <cuda_runtime.h>
#include <cstdint>
#include <math.h>

typedef unsigned long long ull;

#define BB 64
#define SS 512
#define EE 256
#define HH 512
#define GG 2048
#define BSH (BB*SS*HH)
#define NBLK 128

// scan smem (float offsets). XOR-swizzled rows, stride 544.
#define WST 544
#define XOFFS 21760          // 40*544 weights before this
#define REDOFF 21760         // overlaps x region (x fully consumed first)
#define RROW 578
#define RCOL 18
#define SMEM_FLOATS 56576    // 40*544 + 64*544
#define SCAN_SMEM (SMEM_FLOATS*4)

__device__ float g_uproj[BB*SS*GG];
__device__ float g_h[2][BB*HH];
__device__ float g_c[2][BB*HH];
__device__ unsigned int g_ctr;

// ---------------- helpers ----------------
__device__ __forceinline__ void ffma2(ull& d, ull a, ull b) {
    asm("fma.rn.f32x2 %0, %1, %2, %0;" : "+l"(d) : "l"(a), "l"(b));
}
__device__ __forceinline__ ull dup2(float a) {
    ull r; asm("mov.b64 %0, {%1,%1};" : "=l"(r) : "f"(a)); return r;
}
__device__ __forceinline__ float fold2(ull v) {
    float lo, hi;
    asm("mov.b64 {%0,%1}, %2;" : "=f"(lo), "=f"(hi) : "l"(v));
    return lo + hi;
}
__device__ __forceinline__ float sigf(float x) { return 1.0f / (1.0f + expf(-x)); }
// XOR swizzle: permutation, keeps 4-float chunks contiguous & 16B-aligned
__device__ __forceinline__ int skx(int k) { return k ^ ((((k >> 5) & 7)) << 2); }

// ---------------- init ----------------
__global__ void init_state() {
    int i = blockIdx.x * 256 + threadIdx.x;  // 32768
    g_h[0][i] = 0.f;
    g_c[0][i] = 0.f;
    if (i == 0) g_ctr = 0u;
}

// ---------------- u_proj GEMM (FFMA2, proven) ----------------
__global__ void __launch_bounds__(256) gemm_uproj(
    const float* __restrict__ A, const float* __restrict__ W, const float* __restrict__ bias)
{
    __shared__ float As[8][132];
    __shared__ float Bs[8][132];
    const int tid = threadIdx.x;
    const int bm = blockIdx.y * 128, bn = blockIdx.x * 128;
    const int tx = tid & 15, ty = tid >> 4;
    const int lrow = tid >> 1, lk = (tid & 1) * 4;
    const float* Aptr = A + (size_t)(bm + lrow) * EE + lk;
    const float* Wptr = W + (size_t)(bn + lrow) * EE + lk;

    ull acc2[8][4];
#pragma unroll
    for (int r = 0; r < 8; r++)
#pragma unroll
        for (int c = 0; c < 4; c++) acc2[r][c] = 0ull;

    float4 av = *(const float4*)(Aptr);
    float4 bv = *(const float4*)(Wptr);

    for (int k0 = 0; k0 < EE; k0 += 8) {
        __syncthreads();
        As[lk+0][lrow]=av.x; As[lk+1][lrow]=av.y; As[lk+2][lrow]=av.z; As[lk+3][lrow]=av.w;
        Bs[lk+0][lrow]=bv.x; Bs[lk+1][lrow]=bv.y; Bs[lk+2][lrow]=bv.z; Bs[lk+3][lrow]=bv.w;
        __syncthreads();
        if (k0 + 8 < EE) { av = *(const float4*)(Aptr+k0+8); bv = *(const float4*)(Wptr+k0+8); }
#pragma unroll
        for (int kk = 0; kk < 8; kk++) {
            float4 a0 = *(const float4*)&As[kk][ty*8];
            float4 a1 = *(const float4*)&As[kk][ty*8+4];
            ulonglong2 b0 = *(const ulonglong2*)&Bs[kk][tx*8];
            ulonglong2 b1 = *(const ulonglong2*)&Bs[kk][tx*8+4];
            float ar[8] = {a0.x,a0.y,a0.z,a0.w,a1.x,a1.y,a1.z,a1.w};
            ull br2[4] = {b0.x, b0.y, b1.x, b1.y};
#pragma unroll
            for (int r = 0; r < 8; r++) {
                ull ad = dup2(ar[r]);
#pragma unroll
                for (int c = 0; c < 4; c++) ffma2(acc2[r][c], ad, br2[c]);
            }
        }
    }

    float bsr[8];
#pragma unroll
    for (int c = 0; c < 8; c++) bsr[c] = bias[bn + tx*8 + c];
#pragma unroll
    for (int r = 0; r < 8; r++) {
        float accv[8];
#pragma unroll
        for (int c = 0; c < 4; c++) {
            float lo, hi;
            asm("mov.b64 {%0,%1}, %2;" : "=f"(lo), "=f"(hi) : "l"(acc2[r][c]));
            accv[2*c] = lo; accv[2*c+1] = hi;
        }
        float* cp = g_uproj + (size_t)(bm + ty*8 + r) * GG + bn + tx*8;
        float4 o0 = {accv[0]+bsr[0], accv[1]+bsr[1], accv[2]+bsr[2], accv[3]+bsr[3]};
        float4 o1 = {accv[4]+bsr[4], accv[5]+bsr[5], accv[6]+bsr[6], accv[7]+bsr[7]};
        *(float4*)(cp) = o0; *(float4*)(cp + 4) = o1;
    }
}

// ---------------- persistent scan: single-buffer XOR-swizzled FFMA2 GEMM ----------------
// Block: jg = bid>>1 (8 j), bg = bid&1 (32 b). Rows 0..39 = gate*8+jj (gates f,i,o,cT,wd).
// Warp w: rg = w&3 (rows rg*10..+9), khalf = w>>2. Lane: ks8 = lane>>2, cq = lane&3.
// Thread: k-slice (khalf*8+ks8)*32 .. +31, rows rg*10..+9, cols cq*8..+7.
__global__ void __launch_bounds__(256, 1) lstm_scan(
    const float* __restrict__ ts,
    const float* __restrict__ Wall,
    const float* __restrict__ ball,
    const float* __restrict__ Wd,
    const float* __restrict__ bd,
    float* __restrict__ out)
{
    extern __shared__ float sm[];
    const int tid = threadIdx.x;
    const int bid = blockIdx.x;
    const int jbase = (bid >> 1) * 8;
    const int bbase = (bid & 1) * 32;

    // ---- weights -> smem (swizzled), once ----
    for (int idx = tid; idx < 40*512; idx += 256) {
        int row = idx >> 9, k = idx & 511;
        int t = row >> 3, jr = jbase + (row & 7);
        float v = (t < 4) ? __ldg(Wall + (size_t)(t*512 + jr)*512 + k)
                          : __ldg(Wd + (size_t)jr*512 + k);
        sm[row*WST + skx(k)] = v;
    }

    // compute identity
    const int w    = tid >> 5;
    const int lane = tid & 31;
    const int rg   = w & 3;
    const int khalf= w >> 2;
    const int ks8  = lane >> 2;
    const int cq   = lane & 3;
    const int k0   = (khalf*8 + ks8) * 32;   // physical == logical block base

    // phase-B identity
    const int pb = tid >> 3;
    const int pj = tid & 7;
    const int b2 = bbase + pb;
    const int j  = jbase + pj;
    const float bfb = __ldg(ball + j);
    const float bib = __ldg(ball + 512 + j);
    const float bob = __ldg(ball + 1024 + j);
    const float bcb = __ldg(ball + 1536 + j);
    const float bdj = __ldg(bd + j);

    __syncthreads();

    for (int s = 0; s < SS; s++) {
        const float* hsrc = g_h[s & 1];
        const float* csrc = g_c[s & 1];

        // phase-B operand prefetch (independent of staging)
        const float* up = g_uproj + ((size_t)b2 * SS + s) * GG;
        float u0 = __ldg(up + j);
        float u1 = __ldg(up + 512 + j);
        float u2 = __ldg(up + 1024 + j);
        float u3 = __ldg(up + 1536 + j);
        float tv = __ldg(ts + b2 * SS + s);
        float c_old = __ldcg(csrc + b2 * HH + j);

        // ---- stage ALL x (h rows 0-31, c rows 32-63) into swizzled smem ----
#pragma unroll 4
        for (int i = tid; i < 64*128; i += 256) {
            int r = i >> 7;          // smem row 0..63
            int f4 = i & 127;        // float4 index within row
            int k = f4 * 4;
            const float* src = (r < 32) ? (hsrc + (size_t)(bbase + r) * HH + k)
                                        : (csrc + (size_t)(bbase + r - 32) * HH + k);
            float4 v = __ldcg((const float4*)src);
            *(float4*)(sm + XOFFS + r*WST + skx(k)) = v;
        }
        __syncthreads();

        // ---- GEMM: acc[10 rows][8 cols], k-slice of 32 ----
        ull acc[10][8];
#pragma unroll
        for (int rl = 0; rl < 10; rl++)
#pragma unroll
            for (int ci = 0; ci < 8; ci++) acc[rl][ci] = 0ull;

        const float* wb = sm + (rg*10)*WST + k0;
        const float* xb = sm + XOFFS + (cq*8)*WST + k0;

        if (rg < 3) {
#pragma unroll
            for (int cc = 0; cc < 8; cc++) {
                const int ko = ((cc ^ ks8) << 2);   // swizzled physical chunk
                ulonglong2 xv[8];
#pragma unroll
                for (int ci = 0; ci < 8; ci++)
                    xv[ci] = *(const ulonglong2*)(xb + ci*WST + ko);
#pragma unroll
                for (int rl = 0; rl < 10; rl++) {
                    ulonglong2 wv = *(const ulonglong2*)(wb + rl*WST + ko);
#pragma unroll
                    for (int ci = 0; ci < 8; ci++) {
                        ffma2(acc[rl][ci], wv.x, xv[ci].x);
                        ffma2(acc[rl][ci], wv.y, xv[ci].y);
                    }
                }
            }
        } else {
            // rows 30,31 (cT tail) use h; rows 32-39 (W_d) use c
#pragma unroll
            for (int cc = 0; cc < 8; cc++) {
                const int ko = ((cc ^ ks8) << 2);
                ulonglong2 xv[8];
#pragma unroll
                for (int ci = 0; ci < 8; ci++)
                    xv[ci] = *(const ulonglong2*)(xb + ci*WST + ko);
#pragma unroll
                for (int rl = 0; rl < 2; rl++) {
                    ulonglong2 wv = *(const ulonglong2*)(wb + rl*WST + ko);
#pragma unroll
                    for (int ci = 0; ci < 8; ci++) {
                        ffma2(acc[rl][ci], wv.x, xv[ci].x);
                        ffma2(acc[rl][ci], wv.y, xv[ci].y);
                    }
                }
#pragma unroll
                for (int ci = 0; ci < 8; ci++)
                    xv[ci] = *(const ulonglong2*)(xb + (32 + ci)*WST + ko);
#pragma unroll
                for (int rl = 2; rl < 10; rl++) {
                    ulonglong2 wv = *(const ulonglong2*)(wb + rl*WST + ko);
#pragma unroll
                    for (int ci = 0; ci < 8; ci++) {
                        ffma2(acc[rl][ci], wv.x, xv[ci].x);
                        ffma2(acc[rl][ci], wv.y, xv[ci].y);
                    }
                }
            }
        }
        __syncthreads();   // all x reads done; red overlaps x region

        // ---- fold + store partials: red[row*578 + col*18 + slice] ----
        {
            const int slice = khalf*8 + ks8;
#pragma unroll
            for (int rl = 0; rl < 10; rl++) {
                const int row = rg*10 + rl;
#pragma unroll
                for (int ci = 0; ci < 8; ci++) {
                    const int col = cq*8 + ci;
                    sm[REDOFF + row*RROW + col*RCOL + slice] = fold2(acc[rl][ci]);
                }
            }
        }
        __syncthreads();

        // ---- phase B ----
        {
            float p[5];
#pragma unroll
            for (int t = 0; t < 5; t++) {
                const float* base = sm + REDOFF + (t*8 + pj)*RROW + pb*RCOL;
                float s0 = 0.f, s1 = 0.f;
#pragma unroll
                for (int v = 0; v < 8; v += 2) {
                    float2 a = *(const float2*)(base + 2*v);
                    float2 bq = *(const float2*)(base + 2*v + 2);
                    s0 += a.x + a.y;
                    s1 += bq.x + bq.y;
                }
                p[t] = s0 + s1;
            }
            float dec  = 1.0f / logf(2.718281828459045f + tv);
            float cs1  = tanhf(p[4] + bdj);
            float cadj = (c_old - cs1) + cs1 * dec;
            float f  = sigf(p[0] + bfb + u0);
            float ii = sigf(p[1] + bib + u1);
            float o  = sigf(p[2] + bob + u2);
            float ct = tanhf(p[3] + bcb + u3);
            float cn = f * cadj + ii * ct;
            float hn = o * tanhf(cn);

            const int nb = (s + 1) & 1;
            const int ij = b2 * HH + j;
            g_h[nb][ij] = hn;
            g_c[nb][ij] = cn;
            out[((size_t)b2 * SS + s) * HH + j] = hn;
            if (s == SS - 1) {
                out[BSH + ij] = hn;
                out[BSH + BB * HH + ij] = cn;
            }
        }

        // ---- grid barrier ----
        if (s < SS - 1) {
            __threadfence();
            __syncthreads();
            if (tid == 0) {
                atomicAdd(&g_ctr, 1u);
                unsigned tgt = (unsigned)(s + 1) * NBLK;
                volatile unsigned* pc = &g_ctr;
                while (*pc < tgt) { }
            }
            __syncthreads();
        }
    }
}

extern "C" void kernel_launch(void* const* d_in, const int* in_sizes, int n_in,
                              void* d_out, int out_size) {
    const float* inputs = (const float*)d_in[0];
    const float* tstamp = (const float*)d_in[1];
    const float* Wall   = (const float*)d_in[2];
    const float* ball   = (const float*)d_in[3];
    const float* Uall   = (const float*)d_in[4];
    const float* uball  = (const float*)d_in[5];
    const float* Wd     = (const float*)d_in[6];
    const float* bd     = (const float*)d_in[7];
    float* out = (float*)d_out;

    cudaFuncSetAttribute(lstm_scan, cudaFuncAttributeMaxDynamicSharedMemorySize, SCAN_SMEM);

    init_state<<<128, 256>>>();
    dim3 g1(GG / 128, (BB * SS) / 128);
    gemm_uproj<<<g1, 256>>>(inputs, Uall, uball);
    lstm_scan<<<NBLK, 256, SCAN_SMEM>>>(tstamp, Wall, ball, Wd, bd, out);
}

// round 8
// speedup vs baseline: 1.2357x; 1.2357x over previous
#include <cuda_runtime.h>
#include <cstdint>
#include <math.h>

typedef unsigned long long ull;

#define BB 64
#define SS 512
#define EE 256
#define HH 512
#define GG 2048
#define BSH (BB*SS*HH)
#define NBLK 128

// scan smem (float offsets). XOR-swizzled rows, stride 548 (≡1 mod 8 bank-groups).
#define WST 548
#define XOFFS 21920          // 40*548 weights before this
#define REDOFF 21920         // overlaps x region (x fully consumed before red writes)
#define RROW 388             // 32 cols * 12 + 4
#define RCOL 12
#define SMEM_FLOATS 56992    // 40*548 + 64*548
#define SCAN_SMEM (SMEM_FLOATS*4)   // 227968 B

__device__ float g_uproj[BB*SS*GG];
__device__ float g_h[2][BB*HH];
__device__ float g_c[2][BB*HH];
__device__ unsigned int g_ctr;

// ---------------- helpers ----------------
__device__ __forceinline__ void ffma2(ull& d, ull a, ull b) {
    asm("fma.rn.f32x2 %0, %1, %2, %0;" : "+l"(d) : "l"(a), "l"(b));
}
__device__ __forceinline__ ull dup2(float a) {
    ull r; asm("mov.b64 %0, {%1,%1};" : "=l"(r) : "f"(a)); return r;
}
__device__ __forceinline__ float fold2(ull v) {
    float lo, hi;
    asm("mov.b64 {%0,%1}, %2;" : "=f"(lo), "=f"(hi) : "l"(v));
    return lo + hi;
}
__device__ __forceinline__ float sigf(float x) { return 1.0f / (1.0f + expf(-x)); }
// XOR swizzle: permutation of k, 16B-chunk granularity
__device__ __forceinline__ int skx(int k) { return k ^ ((((k >> 5) & 7)) << 2); }
__device__ __forceinline__ uint32_t smem_u32(const void* p) {
    uint32_t a;
    asm("{ .reg .u64 t; cvta.to.shared.u64 t, %1; cvt.u32.u64 %0, t; }" : "=r"(a) : "l"(p));
    return a;
}
__device__ __forceinline__ void cp16(uint32_t dst, const void* src) {
    asm volatile("cp.async.cg.shared.global [%0], [%1], 16;" :: "r"(dst), "l"(src));
}
#define CP_COMMIT() asm volatile("cp.async.commit_group;" ::: "memory")
#define CP_WAIT0()  asm volatile("cp.async.wait_group 0;" ::: "memory")
__device__ __forceinline__ void barn(int id) {
    asm volatile("bar.sync %0, %1;" :: "r"(id), "r"(128) : "memory");
}

// ---------------- init ----------------
__global__ void init_state() {
    int i = blockIdx.x * 256 + threadIdx.x;  // 32768
    g_h[0][i] = 0.f;
    g_c[0][i] = 0.f;
    if (i == 0) g_ctr = 0u;
}

// ---------------- u_proj GEMM (FFMA2, proven) ----------------
__global__ void __launch_bounds__(256) gemm_uproj(
    const float* __restrict__ A, const float* __restrict__ W, const float* __restrict__ bias)
{
    __shared__ float As[8][132];
    __shared__ float Bs[8][132];
    const int tid = threadIdx.x;
    const int bm = blockIdx.y * 128, bn = blockIdx.x * 128;
    const int tx = tid & 15, ty = tid >> 4;
    const int lrow = tid >> 1, lk = (tid & 1) * 4;
    const float* Aptr = A + (size_t)(bm + lrow) * EE + lk;
    const float* Wptr = W + (size_t)(bn + lrow) * EE + lk;

    ull acc2[8][4];
#pragma unroll
    for (int r = 0; r < 8; r++)
#pragma unroll
        for (int c = 0; c < 4; c++) acc2[r][c] = 0ull;

    float4 av = *(const float4*)(Aptr);
    float4 bv = *(const float4*)(Wptr);

    for (int k0 = 0; k0 < EE; k0 += 8) {
        __syncthreads();
        As[lk+0][lrow]=av.x; As[lk+1][lrow]=av.y; As[lk+2][lrow]=av.z; As[lk+3][lrow]=av.w;
        Bs[lk+0][lrow]=bv.x; Bs[lk+1][lrow]=bv.y; Bs[lk+2][lrow]=bv.z; Bs[lk+3][lrow]=bv.w;
        __syncthreads();
        if (k0 + 8 < EE) { av = *(const float4*)(Aptr+k0+8); bv = *(const float4*)(Wptr+k0+8); }
#pragma unroll
        for (int kk = 0; kk < 8; kk++) {
            float4 a0 = *(const float4*)&As[kk][ty*8];
            float4 a1 = *(const float4*)&As[kk][ty*8+4];
            ulonglong2 b0 = *(const ulonglong2*)&Bs[kk][tx*8];
            ulonglong2 b1 = *(const ulonglong2*)&Bs[kk][tx*8+4];
            float ar[8] = {a0.x,a0.y,a0.z,a0.w,a1.x,a1.y,a1.z,a1.w};
            ull br2[4] = {b0.x, b0.y, b1.x, b1.y};
#pragma unroll
            for (int r = 0; r < 8; r++) {
                ull ad = dup2(ar[r]);
#pragma unroll
                for (int c = 0; c < 4; c++) ffma2(acc2[r][c], ad, br2[c]);
            }
        }
    }

    float bsr[8];
#pragma unroll
    for (int c = 0; c < 8; c++) bsr[c] = bias[bn + tx*8 + c];
#pragma unroll
    for (int r = 0; r < 8; r++) {
        float accv[8];
#pragma unroll
        for (int c = 0; c < 4; c++) {
            float lo, hi;
            asm("mov.b64 {%0,%1}, %2;" : "=f"(lo), "=f"(hi) : "l"(acc2[r][c]));
            accv[2*c] = lo; accv[2*c+1] = hi;
        }
        float* cp = g_uproj + (size_t)(bm + ty*8 + r) * GG + bn + tx*8;
        float4 o0 = {accv[0]+bsr[0], accv[1]+bsr[1], accv[2]+bsr[2], accv[3]+bsr[3]};
        float4 o1 = {accv[4]+bsr[4], accv[5]+bsr[5], accv[6]+bsr[6], accv[7]+bsr[7]};
        *(float4*)(cp) = o0; *(float4*)(cp + 4) = o1;
    }
}

// ---------------- persistent scan ----------------
// Block: jg = bid>>1 (8 j), bg = bid&1 (32 b). Rows 0..39 = gate*8+jj (f,i,o,cT,wd).
// Warp w: rg = w&3 (rows rg*10..+9), khalf = w>>2 (k half of 256).
// Lane: ks4 = lane>>3 (k slice of 64 within half), cq = lane&7 (cols cq, cq+8, cq+16, cq+24).
// Warpgroup khalf stages its own k-half via cp.async.cg, gated by named barrier 1/2.
__global__ void __launch_bounds__(256, 1) lstm_scan(
    const float* __restrict__ ts,
    const float* __restrict__ Wall,
    const float* __restrict__ ball,
    const float* __restrict__ Wd,
    const float* __restrict__ bd,
    float* __restrict__ out)
{
    extern __shared__ float sm[];
    const int tid = threadIdx.x;
    const int bid = blockIdx.x;
    const int jbase = (bid >> 1) * 8;
    const int bbase = (bid & 1) * 32;
    const uint32_t smb = smem_u32(sm);

    // ---- weights -> smem (swizzled), once ----
    for (int idx = tid; idx < 40*512; idx += 256) {
        int row = idx >> 9, k = idx & 511;
        int t = row >> 3, jr = jbase + (row & 7);
        float v = (t < 4) ? __ldg(Wall + (size_t)(t*512 + jr)*512 + k)
                          : __ldg(Wd + (size_t)jr*512 + k);
        sm[row*WST + skx(k)] = v;
    }

    // compute identity
    const int w     = tid >> 5;
    const int lane  = tid & 31;
    const int rg    = w & 3;
    const int khalf = w >> 2;
    const int ks4   = lane >> 3;
    const int cq    = lane & 7;
    const int k0    = khalf*256 + ks4*64;

    // staging identity (within my 128-thread warpgroup)
    const int a  = tid & 127;
    const int sr = a >> 1;            // smem x row 0..63
    const int sp = a & 1;             // f4 half of this k-half
    const int kst = khalf * 256;      // my warpgroup's k base

    // phase-B identity
    const int pb = tid >> 3;
    const int pj = tid & 7;
    const int b2 = bbase + pb;
    const int j  = jbase + pj;
    const float bfb = __ldg(ball + j);
    const float bib = __ldg(ball + 512 + j);
    const float bob = __ldg(ball + 1024 + j);
    const float bcb = __ldg(ball + 1536 + j);
    const float bdj = __ldg(bd + j);

    __syncthreads();

    for (int s = 0; s < SS; s++) {
        const float* hsrc = g_h[s & 1];
        const float* csrc = g_c[s & 1];

        // phase-B operand prefetch
        const float* up = g_uproj + ((size_t)b2 * SS + s) * GG;
        float u0 = __ldg(up + j);
        float u1 = __ldg(up + 512 + j);
        float u2 = __ldg(up + 1024 + j);
        float u3 = __ldg(up + 1536 + j);
        float tv = __ldg(ts + b2 * SS + s);
        float c_old = __ldcg(csrc + b2 * HH + j);

        // ---- stage my k-half of x via cp.async.cg (h rows 0-31, c rows 32-63) ----
        {
            const float* srow = (sr < 32) ? (hsrc + (size_t)(bbase + sr) * HH)
                                          : (csrc + (size_t)(bbase + sr - 32) * HH);
#pragma unroll 8
            for (int i = 0; i < 32; i++) {
                int k = kst + (sp*32 + i) * 4;
                uint32_t dst = smb + (uint32_t)((XOFFS + sr*WST + skx(k)) * 4);
                cp16(dst, srow + k);
            }
            CP_COMMIT();
            CP_WAIT0();
            barn(1 + khalf);   // my warpgroup's half fully staged
        }

        // ---- GEMM: acc[10 rows][4 cols], k-slice 64 ----
        ull acc[10][4];
#pragma unroll
        for (int rl = 0; rl < 10; rl++)
#pragma unroll
            for (int ci = 0; ci < 4; ci++) acc[rl][ci] = 0ull;

        const float* wb = sm + (rg*10)*WST + k0;
        const float* xb = sm + XOFFS + cq*WST + k0;

        if (rg < 3) {
#pragma unroll
            for (int cc = 0; cc < 16; cc++) {
                const int swz = (ks4*2 + (cc >> 3)) & 7;
                const int ko  = ((cc ^ swz) << 2);
                ulonglong2 xv[4];
#pragma unroll
                for (int ci = 0; ci < 4; ci++)
                    xv[ci] = *(const ulonglong2*)(xb + (8*ci)*WST + ko);
#pragma unroll
                for (int rl = 0; rl < 10; rl++) {
                    ulonglong2 wv = *(const ulonglong2*)(wb + rl*WST + ko);
#pragma unroll
                    for (int ci = 0; ci < 4; ci++) {
                        ffma2(acc[rl][ci], wv.x, xv[ci].x);
                        ffma2(acc[rl][ci], wv.y, xv[ci].y);
                    }
                }
            }
        } else {
            // rows 30,31 use h; rows 32-39 (W_d) use c (x rows +32)
#pragma unroll
            for (int cc = 0; cc < 16; cc++) {
                const int swz = (ks4*2 + (cc >> 3)) & 7;
                const int ko  = ((cc ^ swz) << 2);
                ulonglong2 hv[4], cv[4];
#pragma unroll
                for (int ci = 0; ci < 4; ci++) {
                    hv[ci] = *(const ulonglong2*)(xb + (8*ci)*WST + ko);
                    cv[ci] = *(const ulonglong2*)(xb + (32 + 8*ci)*WST + ko);
                }
#pragma unroll
                for (int rl = 0; rl < 2; rl++) {
                    ulonglong2 wv = *(const ulonglong2*)(wb + rl*WST + ko);
#pragma unroll
                    for (int ci = 0; ci < 4; ci++) {
                        ffma2(acc[rl][ci], wv.x, hv[ci].x);
                        ffma2(acc[rl][ci], wv.y, hv[ci].y);
                    }
                }
#pragma unroll
                for (int rl = 2; rl < 10; rl++) {
                    ulonglong2 wv = *(const ulonglong2*)(wb + rl*WST + ko);
#pragma unroll
                    for (int ci = 0; ci < 4; ci++) {
                        ffma2(acc[rl][ci], wv.x, cv[ci].x);
                        ffma2(acc[rl][ci], wv.y, cv[ci].y);
                    }
                }
            }
        }
        __syncthreads();   // all x reads done before red overwrites x region

        // ---- fold + store partials: red[row*388 + col*12 + slice] ----
        {
            const int slice = khalf*4 + ks4;
#pragma unroll
            for (int rl = 0; rl < 10; rl++) {
                const int row = rg*10 + rl;
#pragma unroll
                for (int ci = 0; ci < 4; ci++) {
                    const int col = cq + 8*ci;
                    sm[REDOFF + row*RROW + col*RCOL + slice] = fold2(acc[rl][ci]);
                }
            }
        }
        __syncthreads();

        // ---- phase B ----
        {
            float p[5];
#pragma unroll
            for (int t = 0; t < 5; t++) {
                const float* base = sm + REDOFF + (t*8 + pj)*RROW + pb*RCOL;
                float4 aa = *(const float4*)(base);
                float4 bb = *(const float4*)(base + 4);
                p[t] = ((aa.x + aa.y) + (aa.z + aa.w)) + ((bb.x + bb.y) + (bb.z + bb.w));
            }
            float dec  = 1.0f / logf(2.718281828459045f + tv);
            float cs1  = tanhf(p[4] + bdj);
            float cadj = (c_old - cs1) + cs1 * dec;
            float f  = sigf(p[0] + bfb + u0);
            float ii = sigf(p[1] + bib + u1);
            float o  = sigf(p[2] + bob + u2);
            float ct = tanhf(p[3] + bcb + u3);
            float cn = f * cadj + ii * ct;
            float hn = o * tanhf(cn);

            const int nb = (s + 1) & 1;
            const int ij = b2 * HH + j;
            g_h[nb][ij] = hn;
            g_c[nb][ij] = cn;
            out[((size_t)b2 * SS + s) * HH + j] = hn;
            if (s == SS - 1) {
                out[BSH + ij] = hn;
                out[BSH + BB * HH + ij] = cn;
            }
        }

        // ---- grid barrier ----
        if (s < SS - 1) {
            __threadfence();
            __syncthreads();
            if (tid == 0) {
                atomicAdd(&g_ctr, 1u);
                unsigned tgt = (unsigned)(s + 1) * NBLK;
                volatile unsigned* pc = &g_ctr;
                while (*pc < tgt) { }
            }
            __syncthreads();
        }
    }
}

extern "C" void kernel_launch(void* const* d_in, const int* in_sizes, int n_in,
                              void* d_out, int out_size) {
    const float* inputs = (const float*)d_in[0];
    const float* tstamp = (const float*)d_in[1];
    const float* Wall   = (const float*)d_in[2];
    const float* ball   = (const float*)d_in[3];
    const float* Uall   = (const float*)d_in[4];
    const float* uball  = (const float*)d_in[5];
    const float* Wd     = (const float*)d_in[6];
    const float* bd     = (const float*)d_in[7];
    float* out = (float*)d_out;

    cudaFuncSetAttribute(lstm_scan, cudaFuncAttributeMaxDynamicSharedMemorySize, SCAN_SMEM);

    init_state<<<128, 256>>>();
    dim3 g1(GG / 128, (BB * SS) / 128);
    gemm_uproj<<<g1, 256>>>(inputs, Uall, uball);
    lstm_scan<<<NBLK, 256, SCAN_SMEM>>>(tstamp, Wall, ball, Wd, bd, out);
}